// round 16
// baseline (speedup 1.0000x reference)
#include <cuda_runtime.h>
#include <cuda_bf16.h>
#include <cuda_fp16.h>
#include <math.h>
#include <stdint.h>

#define BSZ 8192
#define KN  32
#define DD  512

// ---------------------------------------------------------------------------
// Device scratch
// ---------------------------------------------------------------------------
__device__ __half g_Mth[DD * DD];          // fp16 of Mt[d][j] = sum_e w1[e][j] w2[e][d]
__device__ float g_q2[BSZ * DD];           // x @ M + c
__device__ float g_c[DD];                  // b1 @ w2
__device__ float g_u[DD];                  // b2 @ w1
__device__ float g_s0;                     // b1 . b2

// ---------------------------------------------------------------------------
// Helpers
// ---------------------------------------------------------------------------
__device__ __forceinline__ uint32_t smem_u32(const void* p) {
    uint32_t a;
    asm("{ .reg .u64 t; cvta.to.shared.u64 t, %1; cvt.u32.u64 %0, t; }"
        : "=r"(a) : "l"(p));
    return a;
}
__device__ __forceinline__ void cp16(uint32_t saddr, const void* g) {
    asm volatile("cp.async.cg.shared.global [%0], [%1], 16;"
                 :: "r"(saddr), "l"(g));
}
__device__ __forceinline__ void ldsm4(uint32_t* r, uint32_t addr) {
    asm volatile("ldmatrix.sync.aligned.m8n8.x4.shared.b16 {%0,%1,%2,%3}, [%4];"
                 : "=r"(r[0]), "=r"(r[1]), "=r"(r[2]), "=r"(r[3]) : "r"(addr));
}
__device__ __forceinline__ void mma16816h(float* c, const uint32_t* a,
                                          uint32_t b0, uint32_t b1) {
    asm volatile(
        "mma.sync.aligned.m16n8k16.row.col.f32.f16.f16.f32 "
        "{%0,%1,%2,%3}, {%4,%5,%6,%7}, {%8,%9}, {%0,%1,%2,%3};"
        : "+f"(c[0]), "+f"(c[1]), "+f"(c[2]), "+f"(c[3])
        : "r"(a[0]), "r"(a[1]), "r"(a[2]), "r"(a[3]), "r"(b0), "r"(b1));
}
__device__ __forceinline__ float4 ldcs4(const float4* p) {
    float4 v;
    asm volatile("ld.global.cs.v4.f32 {%0,%1,%2,%3}, [%4];"
                 : "=f"(v.x), "=f"(v.y), "=f"(v.z), "=f"(v.w) : "l"(p));
    return v;
}

// ---------------------------------------------------------------------------
// precompute_all (tensor-core): Mt[d][j] = sum_e w2[e][d]*w1[e][j] via fp16
// HMMA with fp32 accumulate. Per 32-e chunk: LDG fp32 tiles, convert +
// transpose-scatter into fp16 smem ([d][e] / [j][e], 80B pitch), ldmatrix,
// 16 MMA/warp. Software-pipelined LDG. Block tile 64x64, grid (8,8),
// 128 threads = 4 warps (2x2, warp tile 32x32).
// Fused borders (from fp16 tiles): u[j] (by==0, tid<64), c[d] (bx==0,
// tid 64..127), s0 (block 0,0).
// ---------------------------------------------------------------------------
#define PC_PITCH 80
#define PC_STAGE (64 * PC_PITCH)

__global__ __launch_bounds__(128) void precompute_all(
    const float* __restrict__ w1, const float* __restrict__ w2,
    const float* __restrict__ b1, const float* __restrict__ b2) {
    __shared__ __align__(16) char sA[2 * PC_STAGE];   // w2^T fp16 [d][e]
    __shared__ __align__(16) char sB[2 * PC_STAGE];   // w1^T fp16 [j][e]
    __shared__ float sb1[DD], sb2[DD];
    int tid = threadIdx.x;
    int lane = tid & 31;
    int warp = tid >> 5;
    int wm = warp >> 1;               // 0..1 (d half)
    int wn = warp & 1;                // 0..1 (j half)
    int j0 = blockIdx.x * 64, d0 = blockIdx.y * 64;

#pragma unroll
    for (int i = 0; i < 4; i++) {
        sb1[tid + 128 * i] = b1[tid + 128 * i];
        sb2[tid + 128 * i] = b2[tid + 128 * i];
    }

    uint32_t sAb = smem_u32(sA);
    uint32_t sBb = smem_u32(sB);

    // chunk loader: 32 e-rows x 64 cols per matrix = 512 float4 -> 4/thread
    auto ldchunk = [&](int e0, float4* va, float4* vb) {
#pragma unroll
        for (int i = 0; i < 4; i++) {
            int c = tid + 128 * i;
            int r = c >> 4, q = c & 15;
            va[i] = *(const float4*)(w2 + (size_t)(e0 + r) * DD + d0 + q * 4);
            vb[i] = *(const float4*)(w1 + (size_t)(e0 + r) * DD + j0 + q * 4);
        }
    };
    // convert + transpose scatter: element (e=r, col 4q+m) -> smem[col][e]
    auto stchunk = [&](int st, const float4* va, const float4* vb) {
#pragma unroll
        for (int i = 0; i < 4; i++) {
            int c = tid + 128 * i;
            int r = c >> 4, q = c & 15;
            const float* fa = (const float*)&va[i];
            const float* fb = (const float*)&vb[i];
#pragma unroll
            for (int m = 0; m < 4; m++) {
                *(__half*)(sA + st * PC_STAGE + (4 * q + m) * PC_PITCH + r * 2) =
                    __float2half(fa[m]);
                *(__half*)(sB + st * PC_STAGE + (4 * q + m) * PC_PITCH + r * 2) =
                    __float2half(fb[m]);
            }
        }
    };

    float acc[2][4][4];
#pragma unroll
    for (int i = 0; i < 2; i++)
#pragma unroll
        for (int n = 0; n < 4; n++)
#pragma unroll
            for (int q = 0; q < 4; q++) acc[i][n][q] = 0.f;
    float uacc = 0.f, cacc = 0.f;

    int arow  = lane & 15;
    int acol8 = (lane >> 4) * 8;
    int brow  = (lane & 7) + ((lane >> 4) << 3);
    int bcol8 = ((lane >> 3) & 1) * 8;

    float4 va[4], vb[4], van[4], vbn[4];
    ldchunk(0, va, vb);
    stchunk(0, va, vb);

#pragma unroll 1
    for (int t = 0; t < 16; t++) {
        int st = t & 1;
        if (t + 1 < 16) ldchunk((t + 1) * 32, van, vbn);
        __syncthreads();

        uint32_t aB = sAb + st * PC_STAGE;
        uint32_t bB = sBb + st * PC_STAGE;
#pragma unroll
        for (int h = 0; h < 2; h++) {
            uint32_t af[2][4], bf[2][4];
#pragma unroll
            for (int i = 0; i < 2; i++)
                ldsm4(af[i], aB + (uint32_t)(wm * 32 + i * 16 + arow) * PC_PITCH +
                                 (uint32_t)(h * 16 + acol8) * 2);
#pragma unroll
            for (int j = 0; j < 2; j++)
                ldsm4(bf[j], bB + (uint32_t)(wn * 32 + j * 16 + brow) * PC_PITCH +
                                 (uint32_t)(h * 16 + bcol8) * 2);
#pragma unroll
            for (int i = 0; i < 2; i++)
#pragma unroll
                for (int j = 0; j < 2; j++) {
                    mma16816h(acc[i][2 * j],     af[i], bf[j][0], bf[j][1]);
                    mma16816h(acc[i][2 * j + 1], af[i], bf[j][2], bf[j][3]);
                }
        }
        // fused border reductions from fp16 tiles
        if (blockIdx.y == 0 && tid < 64) {
            int e0 = t * 32;
#pragma unroll
            for (int e = 0; e < 32; e++)
                uacc += sb2[e0 + e] *
                        __half2float(*(const __half*)(sB + st * PC_STAGE +
                                                      tid * PC_PITCH + e * 2));
        }
        if (blockIdx.x == 0 && tid >= 64) {
            int e0 = t * 32;
#pragma unroll
            for (int e = 0; e < 32; e++)
                cacc += sb1[e0 + e] *
                        __half2float(*(const __half*)(sA + st * PC_STAGE +
                                                      (tid - 64) * PC_PITCH + e * 2));
        }
        if (t + 1 < 16) stchunk(st ^ 1, van, vbn);
    }

    // epilogue: store fp16 Mt
    int g = lane >> 2, t4 = lane & 3;
#pragma unroll
    for (int i = 0; i < 2; i++) {
        int d = d0 + wm * 32 + i * 16 + g;
#pragma unroll
        for (int n = 0; n < 4; n++) {
            int j = j0 + wn * 32 + n * 8 + 2 * t4;
            __half2 v0 = __floats2half2_rn(acc[i][n][0], acc[i][n][1]);
            __half2 v1 = __floats2half2_rn(acc[i][n][2], acc[i][n][3]);
            *(__half2*)&g_Mth[(size_t)d * DD + j] = v0;
            *(__half2*)&g_Mth[(size_t)(d + 8) * DD + j] = v1;
        }
    }
    if (blockIdx.y == 0 && tid < 64) g_u[j0 + tid] = uacc;
    if (blockIdx.x == 0 && tid >= 64) g_c[d0 + tid - 64] = cacc;
    if (blockIdx.x == 0 && blockIdx.y == 0 && tid < 32) {
        float v = 0.f;
#pragma unroll
        for (int q = 0; q < 16; q++) v += sb1[tid + 32 * q] * sb2[tid + 32 * q];
#pragma unroll
        for (int o = 16; o > 0; o >>= 1) v += __shfl_xor_sync(0xFFFFFFFFu, v, o);
        if (tid == 0) g_s0 = v;
    }
}

// ---------------------------------------------------------------------------
// Pure-fp16 GEMM: q2 = fp16(x) @ fp16(M) + c,  K=512 (16 k32 tiles).
// Block tile 128x256, 512 threads = 16 warps (4m x 4n), warp tile 32x64.
// Grid (2, 64) = 128 blocks, 1 block/SM, 80B-padded smem rows.
// ---------------------------------------------------------------------------
#define NKT 16
#define XH_OFF 0
#define MH_OFF 10240
#define STAGE_STRIDE 30720
#define GSMEM_TOTAL (2 * STAGE_STRIDE + 1024)

__global__ __launch_bounds__(512, 1) void gemm_fused(
    const float* __restrict__ x,
    const __half* __restrict__ Mth,
    float* __restrict__ outf) {
    extern __shared__ char smem[];
    uint32_t sbase = smem_u32(smem);
    int tid = threadIdx.x;
    int lane = tid & 31;
    int warp = tid >> 5;
    int wm = warp >> 2;            // 0..3 (32-row warp tiles)
    int wn = warp & 3;             // 0..3 (64-col warp tiles)
    int bx = blockIdx.x, by = blockIdx.y;

    float* sb = (float*)(smem + 2 * STAGE_STRIDE);
    if (tid < 256) sb[tid] = g_c[bx * 256 + tid];

    float acc[2][8][4];
#pragma unroll
    for (int i = 0; i < 2; i++)
#pragma unroll
        for (int n = 0; n < 8; n++)
#pragma unroll
            for (int q = 0; q < 4; q++) acc[i][n][q] = 0.f;

    int arow  = lane & 15;
    int acol8 = (lane >> 4) * 8;
    int brow  = (lane & 7) + ((lane >> 4) << 3);
    int bcol8 = ((lane >> 3) & 1) * 8;

    auto load_M = [&](int stage, int kt) {
        int kk = kt * 32;
        uint32_t mh = sbase + stage * STAGE_STRIDE + MH_OFF;
#pragma unroll
        for (int i = 0; i < 2; i++) {
            int c = tid + 512 * i;
            int n = c >> 2, q = c & 3;
            cp16(mh + n * 80 + q * 16,
                 Mth + (size_t)(bx * 256 + n) * DD + kk + q * 8);
        }
        asm volatile("cp.async.commit_group;" ::: "memory");
    };

    auto load_x_regs = [&](int kt, float4* vr) {
        int kk = kt * 32;
        int r = tid >> 2, q = tid & 3;
        vr[0] = *(const float4*)(x + (size_t)(by * 128 + r) * DD + kk + q * 8);
        vr[1] = *(const float4*)(x + (size_t)(by * 128 + r) * DD + kk + q * 8 + 4);
    };

    auto store_x = [&](int stage, const float4* vr) {
        uint32_t xh = stage * STAGE_STRIDE + XH_OFF;
        int r = tid >> 2, q = tid & 3;
        float4 v0 = vr[0], v1 = vr[1];
        union { __half2 h[4]; uint4 u; } ph;
        ph.h[0] = __floats2half2_rn(v0.x, v0.y);
        ph.h[1] = __floats2half2_rn(v0.z, v0.w);
        ph.h[2] = __floats2half2_rn(v1.x, v1.y);
        ph.h[3] = __floats2half2_rn(v1.z, v1.w);
        *(uint4*)(smem + xh + r * 80 + q * 16) = ph.u;
    };

    float4 xcur[2];
    load_x_regs(0, xcur);
    load_M(0, 0);
    store_x(0, xcur);

#pragma unroll 1
    for (int kt = 0; kt < NKT; kt++) {
        int cur = kt & 1;
        float4 xnext[2];
        if (kt + 1 < NKT) {
            load_x_regs(kt + 1, xnext);
            load_M(cur ^ 1, kt + 1);
            asm volatile("cp.async.wait_group 1;" ::: "memory");
        } else {
            asm volatile("cp.async.wait_group 0;" ::: "memory");
        }
        __syncthreads();

        uint32_t base = sbase + cur * STAGE_STRIDE;
#pragma unroll
        for (int h = 0; h < 2; h++) {
            uint32_t af[2][4];
#pragma unroll
            for (int i = 0; i < 2; i++) {
                uint32_t rowoff = (uint32_t)(wm * 32 + i * 16 + arow) * 80 +
                                  (uint32_t)(h * 16 + acol8) * 2;
                ldsm4(af[i], base + XH_OFF + rowoff);
            }
#pragma unroll
            for (int jp = 0; jp < 2; jp++) {
                uint32_t bf[2][4];
#pragma unroll
                for (int jj = 0; jj < 2; jj++) {
                    int j = jp * 2 + jj;
                    uint32_t rowoff = (uint32_t)(wn * 64 + j * 16 + brow) * 80 +
                                      (uint32_t)(h * 16 + bcol8) * 2;
                    ldsm4(bf[jj], base + MH_OFF + rowoff);
                }
#pragma unroll
                for (int i = 0; i < 2; i++)
#pragma unroll
                    for (int jj = 0; jj < 2; jj++) {
                        int n = jp * 4 + 2 * jj;
                        mma16816h(acc[i][n],     af[i], bf[jj][0], bf[jj][1]);
                        mma16816h(acc[i][n + 1], af[i], bf[jj][2], bf[jj][3]);
                    }
            }
        }
        if (kt + 1 < NKT) store_x(cur ^ 1, xnext);
        __syncthreads();
    }

    int g = lane >> 2, t4 = lane & 3;
#pragma unroll
    for (int i = 0; i < 2; i++) {
        int r0 = by * 128 + wm * 32 + i * 16 + g;
#pragma unroll
        for (int n = 0; n < 8; n++) {
            int coll = wn * 64 + n * 8 + 2 * t4;
            int colg = bx * 256 + coll;
            float bx0 = sb[coll], bx1 = sb[coll + 1];
            float2 v0 = make_float2(acc[i][n][0] + bx0, acc[i][n][1] + bx1);
            float2 v1 = make_float2(acc[i][n][2] + bx0, acc[i][n][3] + bx1);
            *(float2*)(outf + (size_t)r0 * DD + colg) = v0;
            *(float2*)(outf + (size_t)(r0 + 8) * DD + colg) = v1;
        }
    }
}

// ---------------------------------------------------------------------------
// Attend (R13 config): one warp per row; 128-thread blocks (5 blocks/SM),
// streaming loads for read-once keys/values, PLAIN stores (stcs regressed).
// ---------------------------------------------------------------------------
__global__ __launch_bounds__(128) void attend(const float* __restrict__ x,
                                              const float* __restrict__ keys,
                                              const float* __restrict__ values,
                                              float* __restrict__ out) {
    int warp = (blockIdx.x * blockDim.x + threadIdx.x) >> 5;
    int lane = threadIdx.x & 31;
    if (warp >= BSZ) return;

    const float4* xr  = (const float4*)(x + (size_t)warp * DD);
    const float4* q2r = (const float4*)(g_q2 + (size_t)warp * DD);
    const float4* kb  = (const float4*)(keys + (size_t)warp * KN * DD);
    const float4* vb  = (const float4*)(values + (size_t)warp * KN * DD);
    const float4* ur  = (const float4*)g_u;

    float4 xv[4], qv[4];
#pragma unroll
    for (int i = 0; i < 4; i++) {
        xv[i] = xr[lane + 32 * i];
        qv[i] = q2r[lane + 32 * i];
    }

    float qb = 0.f;
#pragma unroll
    for (int i = 0; i < 4; i++) {
        float4 uv = ur[lane + 32 * i];
        qb += xv[i].x * uv.x + xv[i].y * uv.y + xv[i].z * uv.z + xv[i].w * uv.w;
    }
#pragma unroll
    for (int o = 16; o > 0; o >>= 1) qb += __shfl_xor_sync(0xFFFFFFFFu, qb, o);
    qb += g_s0;

    const float scale = 0.044194173824159216f;  // 1/sqrt(512)

    float myscore = 0.f;
    float4 cur[4];
#pragma unroll
    for (int i = 0; i < 4; i++) cur[i] = ldcs4(&kb[lane + 32 * i]);

#pragma unroll
    for (int k = 0; k < KN; k++) {
        float4 nxt[4];
        if (k + 1 < KN) {
#pragma unroll
            for (int i = 0; i < 4; i++)
                nxt[i] = ldcs4(&kb[(k + 1) * 128 + lane + 32 * i]);
        }
        float p = 0.f;
#pragma unroll
        for (int i = 0; i < 4; i++) {
            p += qv[i].x * cur[i].x + qv[i].y * cur[i].y +
                 qv[i].z * cur[i].z + qv[i].w * cur[i].w;
        }
#pragma unroll
        for (int o = 16; o > 0; o >>= 1) p += __shfl_xor_sync(0xFFFFFFFFu, p, o);
        float s = (p + qb) * scale;
        if (lane == k) myscore = s;
#pragma unroll
        for (int i = 0; i < 4; i++) cur[i] = nxt[i];
    }

    float m = myscore;
#pragma unroll
    for (int o = 16; o > 0; o >>= 1)
        m = fmaxf(m, __shfl_xor_sync(0xFFFFFFFFu, m, o));
    float e = expf(myscore - m);
    float sum = e;
#pragma unroll
    for (int o = 16; o > 0; o >>= 1) sum += __shfl_xor_sync(0xFFFFFFFFu, sum, o);
    float a = e / sum;

    float4 acc[4];
#pragma unroll
    for (int i = 0; i < 4; i++) acc[i] = make_float4(0.f, 0.f, 0.f, 0.f);

#pragma unroll
    for (int k = 0; k < KN; k++) {
        float w = __shfl_sync(0xFFFFFFFFu, a, k);
#pragma unroll
        for (int i = 0; i < 4; i++) {
            float4 vv = ldcs4(&vb[k * 128 + lane + 32 * i]);
            acc[i].x += w * vv.x;
            acc[i].y += w * vv.y;
            acc[i].z += w * vv.z;
            acc[i].w += w * vv.w;
        }
    }

    float4* outr = (float4*)(out + (size_t)warp * DD);
#pragma unroll
    for (int i = 0; i < 4; i++) {
        float4 o;
        o.x = 0.5f * xv[i].x + 0.5f * acc[i].x;
        o.y = 0.5f * xv[i].y + 0.5f * acc[i].y;
        o.z = 0.5f * xv[i].z + 0.5f * acc[i].z;
        o.w = 0.5f * xv[i].w + 0.5f * acc[i].w;
        outr[lane + 32 * i] = o;
    }
}

// ---------------------------------------------------------------------------
extern "C" void kernel_launch(void* const* d_in, const int* in_sizes, int n_in,
                              void* d_out, int out_size) {
    const float* x      = (const float*)d_in[0];
    const float* keys   = (const float*)d_in[1];
    const float* values = (const float*)d_in[2];
    const float* w1     = (const float*)d_in[3];
    const float* b1     = (const float*)d_in[4];
    const float* w2     = (const float*)d_in[5];
    const float* b2     = (const float*)d_in[6];
    float* out = (float*)d_out;

    cudaFuncSetAttribute(gemm_fused, cudaFuncAttributeMaxDynamicSharedMemorySize,
                         GSMEM_TOTAL);

    __half *Mth;
    float *q2;
    cudaGetSymbolAddress((void**)&Mth, g_Mth);
    cudaGetSymbolAddress((void**)&q2, g_q2);

    precompute_all<<<dim3(8, 8), 128>>>(w1, w2, b1, b2);
    gemm_fused<<<dim3(2, 64), 512, GSMEM_TOTAL>>>(x, Mth, q2);
    attend<<<(BSZ * 32) / 128, 128>>>(x, keys, values, out);
}